// round 12
// baseline (speedup 1.0000x reference)
#include <cuda_runtime.h>
#include <cuda_fp16.h>
#include <cstdint>
#include <cstddef>

// out_f32 = f16( f16(A[2048x4096] @ Wp[4096x4096]) @ Wu[4096x16384] )
// Legacy HMMA (tcgen05 rejected by harness ptxas target compute_103).
// R12: fragment double-buffering — ldmatrix for ks+1 overlaps HMMA of ks.

#define BM 128
#define BN 256
#define BK 64
#define STAGES 3
#define PAD 8
#define A_STRIDE (BK + PAD)            // 72 halves
#define B_STRIDE (BN + PAD)            // 264 halves

#define A_STAGE_BYTES (BM * A_STRIDE * 2)                 // 18432
#define B_STAGE_BYTES (BK * B_STRIDE * 2)                 // 33792
#define SMEM_A_OFF    0
#define SMEM_B_OFF    (STAGES * A_STAGE_BYTES)
#define SMEM_DYN      (STAGES * (A_STAGE_BYTES + B_STAGE_BYTES))  // 156672

__device__ __half g_A  [8388608];   // fp16 A_prev
__device__ __half g_Wp [16777216];  // fp16 W_prev
__device__ __half g_Wu [67108864];  // fp16 W_up
__device__ __half g_act[8388608];   // fp16 intermediate

__device__ __forceinline__ uint32_t smem_u32(const void* p) {
    return (uint32_t)__cvta_generic_to_shared(p);
}

// ---------------------------------------------------------------------------
template<int WHICH>
__global__ void f32_to_f16(const float4* __restrict__ src, int n4) {
    __half2* dst = (__half2*)((WHICH == 0) ? g_A : (WHICH == 1) ? g_Wp : g_Wu);
    const int stride = gridDim.x * blockDim.x;
    for (int i = blockIdx.x * blockDim.x + threadIdx.x; i < n4; i += stride) {
        float4 v = src[i];
        dst[2 * i + 0] = __floats2half2_rn(v.x, v.y);
        dst[2 * i + 1] = __floats2half2_rn(v.z, v.w);
    }
}

// ---------------------------------------------------------------------------
// fp16 GEMM: CTA 128x256, 8 warps as 2(M) x 4(N), warp tile 64x64,
// ks-level fragment double-buffering.
template<bool STAGE2>
__global__ __launch_bounds__(256) void gemm_f16_mma(
    float* __restrict__ Cout, int M, int N, int K)
{
    extern __shared__ char smem[];
    const uint32_t sbA = smem_u32(smem) + SMEM_A_OFF;
    const uint32_t sbB = smem_u32(smem) + SMEM_B_OFF;

    const __half* A  = STAGE2 ? (const __half*)g_act : (const __half*)g_A;
    const __half* Bm = STAGE2 ? (const __half*)g_Wu  : (const __half*)g_Wp;

    const int tid  = threadIdx.x;
    const int lane = tid & 31;
    const int warp = tid >> 5;
    const int wr   = warp & 1;
    const int wc   = warp >> 1;

    const int bm = blockIdx.y * BM;
    const int bn = blockIdx.x * BN;

    float acc[4][8][4];
    #pragma unroll
    for (int i = 0; i < 4; i++)
        #pragma unroll
        for (int j = 0; j < 8; j++)
            #pragma unroll
            for (int r = 0; r < 4; r++) acc[i][j][r] = 0.f;

    auto load_tiles = [&](int s, int k0) {
        uint32_t aBase = sbA + s * A_STAGE_BYTES;
        uint32_t bBase = sbB + s * B_STAGE_BYTES;
        #pragma unroll
        for (int i = 0; i < 4; i++) {            // A: 1024 chunks
            int t   = tid + i * 256;
            int row = t >> 3;
            int col = (t & 7) << 3;
            uint32_t dst = aBase + (uint32_t)(row * A_STRIDE + col) * 2;
            const __half* src = A + (size_t)(bm + row) * K + (k0 + col);
            asm volatile("cp.async.cg.shared.global [%0], [%1], 16;"
                         :: "r"(dst), "l"(src) : "memory");
        }
        #pragma unroll
        for (int i = 0; i < 8; i++) {            // B: 2048 chunks
            int t   = tid + i * 256;
            int row = t >> 5;
            int col = (t & 31) << 3;
            uint32_t dst = bBase + (uint32_t)(row * B_STRIDE + col) * 2;
            const __half* src = Bm + (size_t)(k0 + row) * N + (bn + col);
            asm volatile("cp.async.cg.shared.global [%0], [%1], 16;"
                         :: "r"(dst), "l"(src) : "memory");
        }
        asm volatile("cp.async.commit_group;" ::: "memory");
    };

    // Fragment buffers (double-buffered over ks).
    uint32_t a[2][4][4];
    uint32_t b[2][4][4];

    auto load_frags = [&](int buf, int ks, uint32_t aBase, uint32_t bBase) {
        #pragma unroll
        for (int i = 0; i < 4; i++) {
            int row = wr * 64 + i * 16 + (lane & 15);
            int col = ks * 16 + ((lane >> 4) << 3);
            uint32_t addr = aBase + (uint32_t)(row * A_STRIDE + col) * 2;
            asm volatile("ldmatrix.sync.aligned.m8n8.x4.shared.b16 {%0,%1,%2,%3}, [%4];"
                         : "=r"(a[buf][i][0]), "=r"(a[buf][i][1]),
                           "=r"(a[buf][i][2]), "=r"(a[buf][i][3])
                         : "r"(addr));
        }
        #pragma unroll
        for (int jj = 0; jj < 4; jj++) {
            int row = ks * 16 + (lane & 15);
            int col = wc * 64 + jj * 16 + ((lane >> 4) << 3);
            uint32_t addr = bBase + (uint32_t)(row * B_STRIDE + col) * 2;
            asm volatile("ldmatrix.sync.aligned.m8n8.x4.trans.shared.b16 {%0,%1,%2,%3}, [%4];"
                         : "=r"(b[buf][jj][0]), "=r"(b[buf][jj][1]),
                           "=r"(b[buf][jj][2]), "=r"(b[buf][jj][3])
                         : "r"(addr));
        }
    };

    auto mma_frags = [&](int buf) {
        #pragma unroll
        for (int i = 0; i < 4; i++)
            #pragma unroll
            for (int j = 0; j < 8; j++) {
                const uint32_t b0 = b[buf][j >> 1][(j & 1) * 2 + 0];
                const uint32_t b1 = b[buf][j >> 1][(j & 1) * 2 + 1];
                asm volatile(
                    "mma.sync.aligned.m16n8k16.row.col.f32.f16.f16.f32 "
                    "{%0,%1,%2,%3}, {%4,%5,%6,%7}, {%8,%9}, {%0,%1,%2,%3};"
                    : "+f"(acc[i][j][0]), "+f"(acc[i][j][1]),
                      "+f"(acc[i][j][2]), "+f"(acc[i][j][3])
                    : "r"(a[buf][i][0]), "r"(a[buf][i][1]),
                      "r"(a[buf][i][2]), "r"(a[buf][i][3]),
                      "r"(b0), "r"(b1));
            }
    };

    const int ntiles = K / BK;   // 64

    #pragma unroll
    for (int s = 0; s < STAGES - 1; s++)
        load_tiles(s, s * BK);

    for (int kt = 0; kt < ntiles; kt++) {
        const int s = kt % STAGES;
        asm volatile("cp.async.wait_group %0;" :: "n"(STAGES - 2) : "memory");
        __syncthreads();

        uint32_t aBase = sbA + s * A_STAGE_BYTES;
        uint32_t bBase = sbB + s * B_STAGE_BYTES;

        // Start fragment pipeline for this tile, then issue next tile's
        // cp.async (its issue cost hides ldmatrix latency).
        load_frags(0, 0, aBase, bBase);
        if (kt + STAGES - 1 < ntiles)
            load_tiles((kt + STAGES - 1) % STAGES, (kt + STAGES - 1) * BK);

        #pragma unroll
        for (int ks = 0; ks < 4; ks++) {
            const int cur = ks & 1;
            if (ks < 3) load_frags(cur ^ 1, ks + 1, aBase, bBase);
            mma_frags(cur);
        }
    }

    // Epilogue: fp32 acc -> fp16 round (bit-matches reference astype(float16)).
    #pragma unroll
    for (int i = 0; i < 4; i++) {
        #pragma unroll
        for (int j = 0; j < 8; j++) {
            int row0 = bm + wr * 64 + i * 16 + (lane >> 2);
            int col  = bn + wc * 64 + j * 8 + (lane & 3) * 2;
            __half2 h01 = __floats2half2_rn(acc[i][j][0], acc[i][j][1]);
            __half2 h23 = __floats2half2_rn(acc[i][j][2], acc[i][j][3]);
            if (!STAGE2) {
                *(__half2*)(g_act + (size_t)row0 * N + col) = h01;
                *(__half2*)(g_act + (size_t)(row0 + 8) * N + col) = h23;
            } else {
                *(float2*)(Cout + (size_t)row0 * N + col) =
                    make_float2(__half2float(__low2half(h01)), __half2float(__high2half(h01)));
                *(float2*)(Cout + (size_t)(row0 + 8) * N + col) =
                    make_float2(__half2float(__low2half(h23)), __half2float(__high2half(h23)));
            }
        }
    }
}

extern "C" void kernel_launch(void* const* d_in, const int* in_sizes, int n_in,
                              void* d_out, int out_size)
{
    (void)out_size;
    const float* A  = (const float*)d_in[0];
    const float* Wp = (n_in > 1) ? (const float*)d_in[1] : A;
    const float* Wu = (n_in > 2) ? (const float*)d_in[2] : A;
    for (int i = 0; i < n_in; i++) {
        if      (in_sizes[i] == 8388608)  A  = (const float*)d_in[i];
        else if (in_sizes[i] == 16777216) Wp = (const float*)d_in[i];
        else if (in_sizes[i] == 67108864) Wu = (const float*)d_in[i];
    }
    float* out = (float*)d_out;  // [2048, 16384] float32

    cudaFuncSetAttribute(gemm_f16_mma<false>,
                         cudaFuncAttributeMaxDynamicSharedMemorySize, SMEM_DYN);
    cudaFuncSetAttribute(gemm_f16_mma<true>,
                         cudaFuncAttributeMaxDynamicSharedMemorySize, SMEM_DYN);

    const int Bdim = 2048, Ddim = 4096, Kdim = 4096, Fdim = 16384;
    dim3 blk(256);

    f32_to_f16<0><<<1024, 256>>>((const float4*)A,  8388608  / 4);
    f32_to_f16<1><<<2048, 256>>>((const float4*)Wp, 16777216 / 4);
    f32_to_f16<2><<<4096, 256>>>((const float4*)Wu, 67108864 / 4);

    // GEMM1: g_act = f16(A @ Wp)   [2048 x 4096]
    gemm_f16_mma<false><<<dim3(Ddim / BN, Bdim / BM), blk, SMEM_DYN>>>(nullptr, Bdim, Ddim, Kdim);
    // GEMM2: out = f16(g_act @ Wu) [2048 x 16384] stored fp32
    gemm_f16_mma<true><<<dim3(Fdim / BN, Bdim / BM), blk, SMEM_DYN>>>(out, Bdim, Fdim, Ddim);
}

// round 13
// speedup vs baseline: 1.0663x; 1.0663x over previous
#include <cuda_runtime.h>
#include <cuda_fp16.h>
#include <cstdint>
#include <cstddef>

// out_f32 = f16( f16(A[2048x4096] @ Wp[4096x4096]) @ Wu[4096x16384] )
// Legacy HMMA (tcgen05 rejected by harness ptxas target compute_103).
// R13: 512-thread CTA, 16 warps (4/SMSP) to break the ldmatrix/HMMA phase
// convoy; warp tile 64x32 keeps regs <=128 so the full CTA fits the RF.

#define BM 128
#define BN 256
#define BK 64
#define STAGES 3
#define PAD 8
#define A_STRIDE (BK + PAD)            // 72 halves
#define B_STRIDE (BN + PAD)            // 264 halves

#define A_STAGE_BYTES (BM * A_STRIDE * 2)                 // 18432
#define B_STAGE_BYTES (BK * B_STRIDE * 2)                 // 33792
#define SMEM_A_OFF    0
#define SMEM_B_OFF    (STAGES * A_STAGE_BYTES)
#define SMEM_DYN      (STAGES * (A_STAGE_BYTES + B_STAGE_BYTES))  // 156672

__device__ __half g_A  [8388608];   // fp16 A_prev
__device__ __half g_Wp [16777216];  // fp16 W_prev
__device__ __half g_Wu [67108864];  // fp16 W_up
__device__ __half g_act[8388608];   // fp16 intermediate

__device__ __forceinline__ uint32_t smem_u32(const void* p) {
    return (uint32_t)__cvta_generic_to_shared(p);
}

// ---------------------------------------------------------------------------
template<int WHICH>
__global__ void f32_to_f16(const float4* __restrict__ src, int n4) {
    __half2* dst = (__half2*)((WHICH == 0) ? g_A : (WHICH == 1) ? g_Wp : g_Wu);
    const int stride = gridDim.x * blockDim.x;
    for (int i = blockIdx.x * blockDim.x + threadIdx.x; i < n4; i += stride) {
        float4 v = src[i];
        dst[2 * i + 0] = __floats2half2_rn(v.x, v.y);
        dst[2 * i + 1] = __floats2half2_rn(v.z, v.w);
    }
}

// ---------------------------------------------------------------------------
// fp16 GEMM: CTA 128x256, 16 warps as 2(M) x 8(N), warp tile 64x32.
template<bool STAGE2>
__global__ __launch_bounds__(512, 1) void gemm_f16_mma(
    float* __restrict__ Cout, int M, int N, int K)
{
    extern __shared__ char smem[];
    const uint32_t sbA = smem_u32(smem) + SMEM_A_OFF;
    const uint32_t sbB = smem_u32(smem) + SMEM_B_OFF;

    const __half* A  = STAGE2 ? (const __half*)g_act : (const __half*)g_A;
    const __half* Bm = STAGE2 ? (const __half*)g_Wu  : (const __half*)g_Wp;

    const int tid  = threadIdx.x;
    const int lane = tid & 31;
    const int warp = tid >> 5;
    const int wr   = warp & 1;    // 2 warps along M (64 rows each)
    const int wc   = warp >> 1;   // 8 warps along N (32 cols each)

    const int bm = blockIdx.y * BM;
    const int bn = blockIdx.x * BN;

    float acc[4][4][4];
    #pragma unroll
    for (int i = 0; i < 4; i++)
        #pragma unroll
        for (int j = 0; j < 4; j++)
            #pragma unroll
            for (int r = 0; r < 4; r++) acc[i][j][r] = 0.f;

    auto load_tiles = [&](int s, int k0) {
        uint32_t aBase = sbA + s * A_STAGE_BYTES;
        uint32_t bBase = sbB + s * B_STAGE_BYTES;
        #pragma unroll
        for (int i = 0; i < 2; i++) {            // A: 1024 x 16B chunks
            int t   = tid + i * 512;
            int row = t >> 3;
            int col = (t & 7) << 3;
            uint32_t dst = aBase + (uint32_t)(row * A_STRIDE + col) * 2;
            const __half* src = A + (size_t)(bm + row) * K + (k0 + col);
            asm volatile("cp.async.cg.shared.global [%0], [%1], 16;"
                         :: "r"(dst), "l"(src) : "memory");
        }
        #pragma unroll
        for (int i = 0; i < 4; i++) {            // B: 2048 x 16B chunks
            int t   = tid + i * 512;
            int row = t >> 5;
            int col = (t & 31) << 3;
            uint32_t dst = bBase + (uint32_t)(row * B_STRIDE + col) * 2;
            const __half* src = Bm + (size_t)(k0 + row) * N + (bn + col);
            asm volatile("cp.async.cg.shared.global [%0], [%1], 16;"
                         :: "r"(dst), "l"(src) : "memory");
        }
        asm volatile("cp.async.commit_group;" ::: "memory");
    };

    const int ntiles = K / BK;   // 64

    #pragma unroll
    for (int s = 0; s < STAGES - 1; s++)
        load_tiles(s, s * BK);

    for (int kt = 0; kt < ntiles; kt++) {
        const int s = kt % STAGES;
        asm volatile("cp.async.wait_group %0;" :: "n"(STAGES - 2) : "memory");
        __syncthreads();
        if (kt + STAGES - 1 < ntiles)
            load_tiles((kt + STAGES - 1) % STAGES, (kt + STAGES - 1) * BK);

        uint32_t aBase = sbA + s * A_STAGE_BYTES;
        uint32_t bBase = sbB + s * B_STAGE_BYTES;

        #pragma unroll
        for (int ks = 0; ks < 4; ks++) {          // 4 x k16 per BK=64
            uint32_t a[4][4];
            uint32_t b[2][4];
            #pragma unroll
            for (int i = 0; i < 4; i++) {
                int row = wr * 64 + i * 16 + (lane & 15);
                int col = ks * 16 + ((lane >> 4) << 3);
                uint32_t addr = aBase + (uint32_t)(row * A_STRIDE + col) * 2;
                asm volatile("ldmatrix.sync.aligned.m8n8.x4.shared.b16 {%0,%1,%2,%3}, [%4];"
                             : "=r"(a[i][0]), "=r"(a[i][1]), "=r"(a[i][2]), "=r"(a[i][3])
                             : "r"(addr));
            }
            #pragma unroll
            for (int jj = 0; jj < 2; jj++) {      // 32 N cols = 2 x x4.trans
                int row = ks * 16 + (lane & 15);
                int col = wc * 32 + jj * 16 + ((lane >> 4) << 3);
                uint32_t addr = bBase + (uint32_t)(row * B_STRIDE + col) * 2;
                asm volatile("ldmatrix.sync.aligned.m8n8.x4.trans.shared.b16 {%0,%1,%2,%3}, [%4];"
                             : "=r"(b[jj][0]), "=r"(b[jj][1]), "=r"(b[jj][2]), "=r"(b[jj][3])
                             : "r"(addr));
            }
            #pragma unroll
            for (int i = 0; i < 4; i++)
                #pragma unroll
                for (int j = 0; j < 4; j++) {
                    const uint32_t b0 = b[j >> 1][(j & 1) * 2 + 0];
                    const uint32_t b1 = b[j >> 1][(j & 1) * 2 + 1];
                    asm volatile(
                        "mma.sync.aligned.m16n8k16.row.col.f32.f16.f16.f32 "
                        "{%0,%1,%2,%3}, {%4,%5,%6,%7}, {%8,%9}, {%0,%1,%2,%3};"
                        : "+f"(acc[i][j][0]), "+f"(acc[i][j][1]),
                          "+f"(acc[i][j][2]), "+f"(acc[i][j][3])
                        : "r"(a[i][0]), "r"(a[i][1]), "r"(a[i][2]), "r"(a[i][3]),
                          "r"(b0), "r"(b1));
                }
        }
    }

    // Epilogue: fp32 acc -> fp16 round (bit-matches reference astype(float16)).
    #pragma unroll
    for (int i = 0; i < 4; i++) {
        #pragma unroll
        for (int j = 0; j < 4; j++) {
            int row0 = bm + wr * 64 + i * 16 + (lane >> 2);
            int col  = bn + wc * 32 + j * 8 + (lane & 3) * 2;
            __half2 h01 = __floats2half2_rn(acc[i][j][0], acc[i][j][1]);
            __half2 h23 = __floats2half2_rn(acc[i][j][2], acc[i][j][3]);
            if (!STAGE2) {
                *(__half2*)(g_act + (size_t)row0 * N + col) = h01;
                *(__half2*)(g_act + (size_t)(row0 + 8) * N + col) = h23;
            } else {
                *(float2*)(Cout + (size_t)row0 * N + col) =
                    make_float2(__half2float(__low2half(h01)), __half2float(__high2half(h01)));
                *(float2*)(Cout + (size_t)(row0 + 8) * N + col) =
                    make_float2(__half2float(__low2half(h23)), __half2float(__high2half(h23)));
            }
        }
    }
}

extern "C" void kernel_launch(void* const* d_in, const int* in_sizes, int n_in,
                              void* d_out, int out_size)
{
    (void)out_size;
    const float* A  = (const float*)d_in[0];
    const float* Wp = (n_in > 1) ? (const float*)d_in[1] : A;
    const float* Wu = (n_in > 2) ? (const float*)d_in[2] : A;
    for (int i = 0; i < n_in; i++) {
        if      (in_sizes[i] == 8388608)  A  = (const float*)d_in[i];
        else if (in_sizes[i] == 16777216) Wp = (const float*)d_in[i];
        else if (in_sizes[i] == 67108864) Wu = (const float*)d_in[i];
    }
    float* out = (float*)d_out;  // [2048, 16384] float32

    cudaFuncSetAttribute(gemm_f16_mma<false>,
                         cudaFuncAttributeMaxDynamicSharedMemorySize, SMEM_DYN);
    cudaFuncSetAttribute(gemm_f16_mma<true>,
                         cudaFuncAttributeMaxDynamicSharedMemorySize, SMEM_DYN);

    const int Bdim = 2048, Ddim = 4096, Kdim = 4096, Fdim = 16384;
    dim3 blk(512);

    f32_to_f16<0><<<1024, 256>>>((const float4*)A,  8388608  / 4);
    f32_to_f16<1><<<2048, 256>>>((const float4*)Wp, 16777216 / 4);
    f32_to_f16<2><<<4096, 256>>>((const float4*)Wu, 67108864 / 4);

    // GEMM1: g_act = f16(A @ Wp)   [2048 x 4096]
    gemm_f16_mma<false><<<dim3(Ddim / BN, Bdim / BM), blk, SMEM_DYN>>>(nullptr, Bdim, Ddim, Kdim);
    // GEMM2: out = f16(g_act @ Wu) [2048 x 16384] stored fp32
    gemm_f16_mma<true><<<dim3(Fdim / BN, Bdim / BM), blk, SMEM_DYN>>>(out, Bdim, Fdim, Ddim);
}